// round 6
// baseline (speedup 1.0000x reference)
#include <cuda_runtime.h>
#include <cuda_bf16.h>
#include <math.h>

#define B_ 16
#define N_ 512
#define H_ 8
#define E_ 128
#define BH_ (B_*H_)
#define NEGV (-1000000000.0f)
#define SCALE_ 0.08838834764831845f

// Intermediates as packed bf16x2 (unsigned) arrays. hi/lo split pairs.
__device__ unsigned g_qh[BH_*N_*E_/2];
__device__ unsigned g_ql[BH_*N_*E_/2];
__device__ unsigned g_kh[BH_*N_*E_/2];
__device__ unsigned g_kl[BH_*N_*E_/2];
__device__ unsigned g_vh[BH_*N_*E_/2];
__device__ unsigned g_vl[BH_*N_*E_/2];
__device__ unsigned g_yh[BH_*N_*E_/2];
__device__ unsigned g_yl[BH_*N_*E_/2];
__device__ unsigned g_woh[E_*1024/2];
__device__ unsigned g_wol[E_*1024/2];

// ---------------------------------------------------------------------------
// helpers
// ---------------------------------------------------------------------------
__device__ __forceinline__ unsigned smem_u32(const void* p) {
    unsigned r;
    asm("{ .reg .u64 t; cvta.to.shared.u64 t, %1; cvt.u32.u64 %0, t; }" : "=r"(r) : "l"(p));
    return r;
}
__device__ __forceinline__ void ldsm4(unsigned r[4], unsigned addr) {
    asm volatile("ldmatrix.sync.aligned.m8n8.x4.shared.b16 {%0,%1,%2,%3}, [%4];"
        : "=r"(r[0]), "=r"(r[1]), "=r"(r[2]), "=r"(r[3]) : "r"(addr));
}
__device__ __forceinline__ void ldsm4t(unsigned r[4], unsigned addr) {
    asm volatile("ldmatrix.sync.aligned.m8n8.x4.trans.shared.b16 {%0,%1,%2,%3}, [%4];"
        : "=r"(r[0]), "=r"(r[1]), "=r"(r[2]), "=r"(r[3]) : "r"(addr));
}
__device__ __forceinline__ void mma16816(float c[4], const unsigned a[4],
                                         unsigned b0, unsigned b1) {
    asm volatile("mma.sync.aligned.m16n8k16.row.col.f32.bf16.bf16.f32 "
        "{%0,%1,%2,%3}, {%4,%5,%6,%7}, {%8,%9}, {%0,%1,%2,%3};"
        : "+f"(c[0]), "+f"(c[1]), "+f"(c[2]), "+f"(c[3])
        : "r"(a[0]), "r"(a[1]), "r"(a[2]), "r"(a[3]), "r"(b0), "r"(b1));
}
__device__ __forceinline__ unsigned pack_hi(float a, float b) {
    __nv_bfloat162 h = __floats2bfloat162_rn(a, b);
    return *(unsigned*)&h;
}
__device__ __forceinline__ unsigned pack_lo(float a, float b, unsigned hi) {
    __nv_bfloat162 h = *(__nv_bfloat162*)&hi;
    __nv_bfloat162 l = __floats2bfloat162_rn(a - __bfloat162float(__low2bfloat16(h)),
                                             b - __bfloat162float(__high2bfloat16(h)));
    return *(unsigned*)&l;
}

// fp32 tile -> split bf16 hi/lo smem (272B row stride). 256 threads.
__device__ __forceinline__ void load_split(const float* __restrict__ src,
        size_t stride, char* smc, int offH, int offL, int rows, int tid)
{
    const int iters = rows >> 3;
    for (int i = 0; i < iters; i++) {
        int idx = tid + (i << 8);
        int r = idx >> 5, c4 = idx & 31;
        float4 v = *(const float4*)(src + (size_t)r * stride + c4 * 4);
        unsigned h0 = pack_hi(v.x, v.y), h1 = pack_hi(v.z, v.w);
        unsigned l0 = pack_lo(v.x, v.y, h0), l1 = pack_lo(v.z, v.w, h1);
        *(uint2*)(smc + offH + r * 272 + c4 * 8) = make_uint2(h0, h1);
        *(uint2*)(smc + offL + r * 272 + c4 * 8) = make_uint2(l0, l1);
    }
}

// packed-bf16 tile copy: global (row stride 64 unsigned) -> smem 272B stride
__device__ __forceinline__ void copy_tile(const unsigned* __restrict__ srcH,
        const unsigned* __restrict__ srcL, char* smc, int offH, int offL,
        int rows, int tid)
{
    const int iters = rows >> 4;      // rows*16 uint4 / 256
    for (int i = 0; i < iters; i++) {
        int idx = tid + (i << 8);
        int r = idx >> 4, c = idx & 15;
        *(uint4*)(smc + offH + r * 272 + c * 16) = *(const uint4*)(srcH + (size_t)r * 64 + c * 4);
        *(uint4*)(smc + offL + r * 272 + c * 16) = *(const uint4*)(srcL + (size_t)r * 64 + c * 4);
    }
}

// ---------------------------------------------------------------------------
// Kernel 0: split Wo into bf16 hi/lo (runs once per launch, ~3us)
// ---------------------------------------------------------------------------
__global__ void wsplit_kernel(const float* __restrict__ Wo) {
    int i = blockIdx.x * 256 + threadIdx.x;   // 0..65535
    float2 v = *(const float2*)(Wo + 2 * i);
    unsigned h = pack_hi(v.x, v.y);
    g_woh[i] = h;
    g_wol[i] = pack_lo(v.x, v.y, h);
}

// ---------------------------------------------------------------------------
// Kernel 1: QKV projection, mma.sync 3-term, term-major issue.
// Writes q(scaled)/k/v as packed bf16 hi/lo in [b,h,n,e].
// ---------------------------------------------------------------------------
#define QG_XH 0
#define QG_XL 34816
#define QG_WH 69632
#define QG_WL 104448
#define SMEM_QKV 139264

__global__ __launch_bounds__(256, 1) void qkv_mma_kernel(
    const float* __restrict__ x,
    const float* __restrict__ Wq, const float* __restrict__ bq,
    const float* __restrict__ Wk, const float* __restrict__ bk,
    const float* __restrict__ Wv, const float* __restrict__ bv)
{
    extern __shared__ char smc[];
    const unsigned sb = smem_u32(smc);

    const int which = blockIdx.z;
    const float* __restrict__ W    = (which == 0) ? Wq : (which == 1) ? Wk : Wv;
    const float* __restrict__ bias = (which == 0) ? bq : (which == 1) ? bk : bv;
    unsigned* __restrict__ dH = (which == 0) ? g_qh : (which == 1) ? g_kh : g_vh;
    unsigned* __restrict__ dL = (which == 0) ? g_ql : (which == 1) ? g_kl : g_vl;

    const int tid  = threadIdx.x;
    const int lane = tid & 31;
    const int wid  = tid >> 5;
    const int wm   = wid >> 1;
    const int wn   = wid & 1;
    const int gid  = lane >> 2;
    const int tig  = lane & 3;

    const int row0 = blockIdx.x << 7;
    const int col0 = blockIdx.y << 7;

    const int a_row = (lane & 15);
    const int a_col = ((lane >> 4) << 3);
    const int b_key = (lane & 7) + ((lane >> 4) << 3);
    const int b_ecol = (((lane >> 3) & 1) << 3);

    load_split(x + (size_t)row0 * E_, E_, smc, QG_XH, QG_XL, 128, tid);
    load_split(W + (size_t)col0 * E_, E_, smc, QG_WH, QG_WL, 128, tid);
    __syncthreads();

    float acc[2][8][4] = {};
    #pragma unroll
    for (int k = 0; k < 8; k++) {
        unsigned ah[2][4], al[2][4], bh4[4][4], bl4[4][4];
        #pragma unroll
        for (int mf = 0; mf < 2; mf++) {
            unsigned ao = (unsigned)((wm * 32 + mf * 16 + a_row) * 272 + (k * 16 + a_col) * 2);
            ldsm4(ah[mf], sb + QG_XH + ao);
            ldsm4(al[mf], sb + QG_XL + ao);
        }
        #pragma unroll
        for (int ng = 0; ng < 4; ng++) {
            unsigned bo = (unsigned)((wn * 64 + ng * 16 + b_key) * 272 + (k * 16 + b_ecol) * 2);
            ldsm4(bh4[ng], sb + QG_WH + bo);
            ldsm4(bl4[ng], sb + QG_WL + bo);
        }
        // term hh (16 independent accs), then hl, then lh
        #pragma unroll
        for (int ng = 0; ng < 4; ng++)
            #pragma unroll
            for (int mf = 0; mf < 2; mf++) {
                mma16816(acc[mf][2*ng],   ah[mf], bh4[ng][0], bh4[ng][1]);
                mma16816(acc[mf][2*ng+1], ah[mf], bh4[ng][2], bh4[ng][3]);
            }
        #pragma unroll
        for (int ng = 0; ng < 4; ng++)
            #pragma unroll
            for (int mf = 0; mf < 2; mf++) {
                mma16816(acc[mf][2*ng],   ah[mf], bl4[ng][0], bl4[ng][1]);
                mma16816(acc[mf][2*ng+1], ah[mf], bl4[ng][2], bl4[ng][3]);
            }
        #pragma unroll
        for (int ng = 0; ng < 4; ng++)
            #pragma unroll
            for (int mf = 0; mf < 2; mf++) {
                mma16816(acc[mf][2*ng],   al[mf], bh4[ng][0], bh4[ng][1]);
                mma16816(acc[mf][2*ng+1], al[mf], bh4[ng][2], bh4[ng][3]);
            }
    }

    const int hh = col0 >> 7;
    const float sc = (which == 0) ? SCALE_ : 1.0f;
    #pragma unroll
    for (int mf = 0; mf < 2; mf++) {
        const int lr0 = wm * 32 + mf * 16 + gid;
        #pragma unroll
        for (int nf = 0; nf < 8; nf++) {
            const int cb = wn * 64 + nf * 8 + 2 * tig;
            const float b0v = bias[col0 + cb], b1v = bias[col0 + cb + 1];
            float v0 = (acc[mf][nf][0] + b0v) * sc;
            float v1 = (acc[mf][nf][1] + b1v) * sc;
            float v2 = (acc[mf][nf][2] + b0v) * sc;
            float v3 = (acc[mf][nf][3] + b1v) * sc;
            int rw = row0 + lr0;
            int b = rw >> 9, n = rw & 511;
            size_t u = (((size_t)(b * H_ + hh) * N_ + n) << 6) + (cb >> 1);
            unsigned h0 = pack_hi(v0, v1);
            dH[u] = h0; dL[u] = pack_lo(v0, v1, h0);
            rw += 8; b = rw >> 9; n = rw & 511;
            u = (((size_t)(b * H_ + hh) * N_ + n) << 6) + (cb >> 1);
            unsigned h1 = pack_hi(v2, v3);
            dH[u] = h1; dL[u] = pack_lo(v2, v3, h1);
        }
    }
}

// ---------------------------------------------------------------------------
// Kernel 2: flash attention, mma.sync, term-major issue, packed bf16 inputs.
// ---------------------------------------------------------------------------
#define QH_OFF   0
#define QL_OFF   34816
#define KH_OFF   69632
#define KL_OFF   104448
#define PH_OFF   139264
#define PL_OFF   174080
#define MK_OFF   208896
#define MS_OFF   210944
#define LS_OFF   211456
#define WMAX_OFF 211968
#define WSUM_OFF 212992
#define SMEM_ATTN 214016

__global__ __launch_bounds__(256, 1) void attn_mma_kernel(
    const float* __restrict__ dist, const float* __restrict__ mask)
{
    extern __shared__ char smc[];
    const unsigned sb = smem_u32(smc);
    float* mk   = (float*)(smc + MK_OFF);
    float* m_s  = (float*)(smc + MS_OFF);
    float* l_s  = (float*)(smc + LS_OFF);
    float* wmax = (float*)(smc + WMAX_OFF);
    float* wsum = (float*)(smc + WSUM_OFF);

    const int tid  = threadIdx.x;
    const int lane = tid & 31;
    const int wid  = tid >> 5;
    const int wm   = wid >> 1;
    const int wn   = wid & 1;
    const int gid  = lane >> 2;
    const int tig  = lane & 3;

    const int q0 = blockIdx.x << 7;
    const int bh = blockIdx.y;
    const int b  = bh >> 3;

    for (int i = tid; i < 512; i += 256) mk[i] = mask[b * 512 + i];
    if (tid < 128) { m_s[tid] = -3.0e38f; l_s[tid] = 0.f; }

    copy_tile(g_qh + (((size_t)bh * N_ + q0) << 6), g_ql + (((size_t)bh * N_ + q0) << 6),
              smc, QH_OFF, QL_OFF, 128, tid);

    float o[16][4] = {};

    const int a_row = (lane & 15);
    const int a_col = ((lane >> 4) << 3);
    const int b_key = (lane & 7) + ((lane >> 4) << 3);
    const int b_ecol = (((lane >> 3) & 1) << 3);
    const int v_key = (lane & 7) + (((lane >> 3) & 1) << 3);
    const int v_ecol = ((lane >> 4) << 3);

    for (int kt = 0; kt < 4; kt++) {
        const size_t kb = ((size_t)bh * N_ + kt * 128) << 6;
        copy_tile(g_kh + kb, g_kl + kb, smc, KH_OFF, KL_OFF, 128, tid);
        __syncthreads();

        float acc[2][8][4] = {};
        #pragma unroll
        for (int k = 0; k < 8; k++) {
            unsigned ah[2][4], al[2][4], bh4[4][4], bl4[4][4];
            #pragma unroll
            for (int mf = 0; mf < 2; mf++) {
                unsigned ao = (unsigned)((wm * 32 + mf * 16 + a_row) * 272 + (k * 16 + a_col) * 2);
                ldsm4(ah[mf], sb + QH_OFF + ao);
                ldsm4(al[mf], sb + QL_OFF + ao);
            }
            #pragma unroll
            for (int ng = 0; ng < 4; ng++) {
                unsigned bo = (unsigned)((wn * 64 + ng * 16 + b_key) * 272 + (k * 16 + b_ecol) * 2);
                ldsm4(bh4[ng], sb + KH_OFF + bo);
                ldsm4(bl4[ng], sb + KL_OFF + bo);
            }
            #pragma unroll
            for (int ng = 0; ng < 4; ng++)
                #pragma unroll
                for (int mf = 0; mf < 2; mf++) {
                    mma16816(acc[mf][2*ng],   ah[mf], bh4[ng][0], bh4[ng][1]);
                    mma16816(acc[mf][2*ng+1], ah[mf], bh4[ng][2], bh4[ng][3]);
                }
            #pragma unroll
            for (int ng = 0; ng < 4; ng++)
                #pragma unroll
                for (int mf = 0; mf < 2; mf++) {
                    mma16816(acc[mf][2*ng],   ah[mf], bl4[ng][0], bl4[ng][1]);
                    mma16816(acc[mf][2*ng+1], ah[mf], bl4[ng][2], bl4[ng][3]);
                }
            #pragma unroll
            for (int ng = 0; ng < 4; ng++)
                #pragma unroll
                for (int mf = 0; mf < 2; mf++) {
                    mma16816(acc[mf][2*ng],   al[mf], bh4[ng][0], bh4[ng][1]);
                    mma16816(acc[mf][2*ng+1], al[mf], bh4[ng][2], bh4[ng][3]);
                }
        }

        float mx[2][2] = {{-3.0e38f, -3.0e38f}, {-3.0e38f, -3.0e38f}};
        #pragma unroll
        for (int mf = 0; mf < 2; mf++) {
            const int lr0 = wm * 32 + mf * 16 + gid;
            #pragma unroll
            for (int nf = 0; nf < 8; nf++) {
                const int cb = wn * 64 + nf * 8 + 2 * tig;
                const int gcol = kt * 128 + cb;
                const float* dp = dist + ((size_t)b * N_ + q0 + lr0) * N_ + gcol;
                float2 d0 = *(const float2*)dp;
                float2 d1 = *(const float2*)(dp + 8 * N_);
                const bool k0 = (mk[gcol] != 0.f), k1 = (mk[gcol + 1] != 0.f);
                float s0 = k0 ? acc[mf][nf][0] + d0.x : NEGV;
                float s1 = k1 ? acc[mf][nf][1] + d0.y : NEGV;
                float s2 = k0 ? acc[mf][nf][2] + d1.x : NEGV;
                float s3 = k1 ? acc[mf][nf][3] + d1.y : NEGV;
                acc[mf][nf][0] = s0; acc[mf][nf][1] = s1;
                acc[mf][nf][2] = s2; acc[mf][nf][3] = s3;
                mx[mf][0] = fmaxf(mx[mf][0], fmaxf(s0, s1));
                mx[mf][1] = fmaxf(mx[mf][1], fmaxf(s2, s3));
            }
        }
        #pragma unroll
        for (int mf = 0; mf < 2; mf++)
            #pragma unroll
            for (int hh = 0; hh < 2; hh++) {
                float m = mx[mf][hh];
                m = fmaxf(m, __shfl_xor_sync(0xffffffffu, m, 1));
                m = fmaxf(m, __shfl_xor_sync(0xffffffffu, m, 2));
                mx[mf][hh] = m;
            }
        if (tig == 0) {
            #pragma unroll
            for (int mf = 0; mf < 2; mf++)
                #pragma unroll
                for (int hh = 0; hh < 2; hh++)
                    wmax[wn * 128 + wm * 32 + mf * 16 + gid + 8 * hh] = mx[mf][hh];
        }
        __syncthreads();

        const size_t vb = ((size_t)bh * N_ + kt * 128) << 6;
        copy_tile(g_vh + vb, g_vl + vb, smc, KH_OFF, KL_OFF, 128, tid);

        float mnew[2][2], alph[2][2], rs[2][2] = {};
        #pragma unroll
        for (int mf = 0; mf < 2; mf++)
            #pragma unroll
            for (int hh = 0; hh < 2; hh++) {
                const int r = wm * 32 + mf * 16 + gid + 8 * hh;
                const float mo = m_s[r];
                const float mn = fmaxf(fmaxf(wmax[r], wmax[128 + r]), mo);
                mnew[mf][hh] = mn;
                alph[mf][hh] = __expf(mo - mn);
            }
        #pragma unroll
        for (int mf = 0; mf < 2; mf++) {
            const int lr0 = wm * 32 + mf * 16 + gid;
            #pragma unroll
            for (int nf = 0; nf < 8; nf++) {
                const int cb = wn * 64 + nf * 8 + 2 * tig;
                float p0 = __expf(acc[mf][nf][0] - mnew[mf][0]);
                float p1 = __expf(acc[mf][nf][1] - mnew[mf][0]);
                float p2 = __expf(acc[mf][nf][2] - mnew[mf][1]);
                float p3 = __expf(acc[mf][nf][3] - mnew[mf][1]);
                rs[mf][0] += p0 + p1;
                rs[mf][1] += p2 + p3;
                unsigned hA = pack_hi(p0, p1), hB = pack_hi(p2, p3);
                *(unsigned*)(smc + PH_OFF + lr0 * 272 + cb * 2)       = hA;
                *(unsigned*)(smc + PL_OFF + lr0 * 272 + cb * 2)       = pack_lo(p0, p1, hA);
                *(unsigned*)(smc + PH_OFF + (lr0 + 8) * 272 + cb * 2) = hB;
                *(unsigned*)(smc + PL_OFF + (lr0 + 8) * 272 + cb * 2) = pack_lo(p2, p3, hB);
            }
        }
        #pragma unroll
        for (int mf = 0; mf < 2; mf++)
            #pragma unroll
            for (int hh = 0; hh < 2; hh++) {
                float s = rs[mf][hh];
                s += __shfl_xor_sync(0xffffffffu, s, 1);
                s += __shfl_xor_sync(0xffffffffu, s, 2);
                rs[mf][hh] = s;
            }
        if (tig == 0) {
            #pragma unroll
            for (int mf = 0; mf < 2; mf++)
                #pragma unroll
                for (int hh = 0; hh < 2; hh++)
                    wsum[wn * 128 + wm * 32 + mf * 16 + gid + 8 * hh] = rs[mf][hh];
        }
        {
            const int ro0 = wid * 16 + gid;
            const float mo0 = m_s[ro0];
            const float a0 = __expf(mo0 - fmaxf(fmaxf(wmax[ro0], wmax[128 + ro0]), mo0));
            const int ro1 = ro0 + 8;
            const float mo1 = m_s[ro1];
            const float a1 = __expf(mo1 - fmaxf(fmaxf(wmax[ro1], wmax[128 + ro1]), mo1));
            #pragma unroll
            for (int nf = 0; nf < 16; nf++) {
                o[nf][0] *= a0; o[nf][1] *= a0;
                o[nf][2] *= a1; o[nf][3] *= a1;
            }
        }
        __syncthreads();

        if (wn == 0 && tig == 0) {
            #pragma unroll
            for (int mf = 0; mf < 2; mf++)
                #pragma unroll
                for (int hh = 0; hh < 2; hh++) {
                    const int r = wm * 32 + mf * 16 + gid + 8 * hh;
                    m_s[r] = mnew[mf][hh];
                    l_s[r] = alph[mf][hh] * l_s[r] + wsum[r] + wsum[128 + r];
                }
        }

        // PV: term-major in ng-groups of 4 (8 independent accs per term pass)
        #pragma unroll
        for (int k = 0; k < 8; k++) {
            unsigned ph4[4], pl4[4];
            unsigned po = (unsigned)((wid * 16 + a_row) * 272 + (k * 16 + a_col) * 2);
            ldsm4(ph4, sb + PH_OFF + po);
            ldsm4(pl4, sb + PL_OFF + po);
            #pragma unroll
            for (int g2 = 0; g2 < 2; g2++) {
                unsigned vh4[4][4], vl4[4][4];
                #pragma unroll
                for (int j = 0; j < 4; j++) {
                    const int ng = g2 * 4 + j;
                    unsigned vo = (unsigned)((k * 16 + v_key) * 272 + (ng * 16 + v_ecol) * 2);
                    ldsm4t(vh4[j], sb + KH_OFF + vo);
                    ldsm4t(vl4[j], sb + KL_OFF + vo);
                }
                #pragma unroll
                for (int j = 0; j < 4; j++) {
                    const int ng = g2 * 4 + j;
                    mma16816(o[2*ng],   ph4, vh4[j][0], vh4[j][1]);
                    mma16816(o[2*ng+1], ph4, vh4[j][2], vh4[j][3]);
                }
                #pragma unroll
                for (int j = 0; j < 4; j++) {
                    const int ng = g2 * 4 + j;
                    mma16816(o[2*ng],   ph4, vl4[j][0], vl4[j][1]);
                    mma16816(o[2*ng+1], ph4, vl4[j][2], vl4[j][3]);
                }
                #pragma unroll
                for (int j = 0; j < 4; j++) {
                    const int ng = g2 * 4 + j;
                    mma16816(o[2*ng],   pl4, vh4[j][0], vh4[j][1]);
                    mma16816(o[2*ng+1], pl4, vh4[j][2], vh4[j][3]);
                }
            }
        }
        __syncthreads();
    }

    // normalize, split to bf16 hi/lo, store packed
    const int ro0 = wid * 16 + gid;
    const float li0 = 1.f / l_s[ro0];
    const float li1 = 1.f / l_s[ro0 + 8];
    unsigned* YH = g_yh + (((size_t)bh * N_ + q0) << 6);
    unsigned* YL = g_yl + (((size_t)bh * N_ + q0) << 6);
    #pragma unroll
    for (int nf = 0; nf < 16; nf++) {
        const int e = nf * 8 + 2 * tig;
        float v0 = o[nf][0] * li0, v1 = o[nf][1] * li0;
        float v2 = o[nf][2] * li1, v3 = o[nf][3] * li1;
        unsigned h0 = pack_hi(v0, v1), h1 = pack_hi(v2, v3);
        YH[(size_t)ro0 * 64 + (e >> 1)]       = h0;
        YL[(size_t)ro0 * 64 + (e >> 1)]       = pack_lo(v0, v1, h0);
        YH[(size_t)(ro0 + 8) * 64 + (e >> 1)] = h1;
        YL[(size_t)(ro0 + 8) * 64 + (e >> 1)] = pack_lo(v2, v3, h1);
    }
}

// ---------------------------------------------------------------------------
// Kernel 3: out = Y @ Wo^T + bo, * mask. Packed bf16 inputs, term-major.
// ---------------------------------------------------------------------------
#define OG_AH 0
#define OG_AL 17408
#define OG_BH 34816
#define OG_BL 69632
#define SMEM_OPROJ 104448

__global__ __launch_bounds__(256, 1) void oproj_mma_kernel(
    const float* __restrict__ bo,
    const float* __restrict__ mask, float* __restrict__ out)
{
    extern __shared__ char smc[];
    const unsigned sb = smem_u32(smc);

    const int tid  = threadIdx.x;
    const int lane = tid & 31;
    const int wid  = tid >> 5;
    const int wm   = wid >> 1;
    const int wn   = wid & 1;
    const int gid  = lane >> 2;
    const int tig  = lane & 3;

    const int row0 = blockIdx.x << 6;
    const int b    = row0 >> 9;
    const int n0   = row0 & 511;

    const int a_row = (lane & 15);
    const int a_col = ((lane >> 4) << 3);
    const int b_key = (lane & 7) + ((lane >> 4) << 3);
    const int b_ecol = (((lane >> 3) & 1) << 3);

    float acc[8][4] = {};

    for (int h = 0; h < 8; h++) {
        const size_t ab = ((size_t)(b * H_ + h) * N_ + n0) << 6;
        copy_tile(g_yh + ab, g_yl + ab, smc, OG_AH, OG_AL, 64, tid);
        // B: 128 out-cols x 128 k (source row stride 512 unsigned)
        #pragma unroll
        for (int i = 0; i < 8; i++) {
            int idx = tid + (i << 8);
            int r = idx >> 4, c = idx & 15;
            size_t su = (size_t)r * 512 + h * 64 + c * 4;
            *(uint4*)(smc + OG_BH + r * 272 + c * 16) = *(const uint4*)(g_woh + su);
            *(uint4*)(smc + OG_BL + r * 272 + c * 16) = *(const uint4*)(g_wol + su);
        }
        __syncthreads();

        #pragma unroll
        for (int k = 0; k < 8; k++) {
            unsigned ah[4], al[4], bh4[4][4], bl4[4][4];
            unsigned ao = (unsigned)((wm * 16 + a_row) * 272 + (k * 16 + a_col) * 2);
            ldsm4(ah, sb + OG_AH + ao);
            ldsm4(al, sb + OG_AL + ao);
            #pragma unroll
            for (int ng = 0; ng < 4; ng++) {
                unsigned bo_ = (unsigned)((wn * 64 + ng * 16 + b_key) * 272 + (k * 16 + b_ecol) * 2);
                ldsm4(bh4[ng], sb + OG_BH + bo_);
                ldsm4(bl4[ng], sb + OG_BL + bo_);
            }
            #pragma unroll
            for (int ng = 0; ng < 4; ng++) {
                mma16816(acc[2*ng],   ah, bh4[ng][0], bh4[ng][1]);
                mma16816(acc[2*ng+1], ah, bh4[ng][2], bh4[ng][3]);
            }
            #pragma unroll
            for (int ng = 0; ng < 4; ng++) {
                mma16816(acc[2*ng],   ah, bl4[ng][0], bl4[ng][1]);
                mma16816(acc[2*ng+1], ah, bl4[ng][2], bl4[ng][3]);
            }
            #pragma unroll
            for (int ng = 0; ng < 4; ng++) {
                mma16816(acc[2*ng],   al, bh4[ng][0], bh4[ng][1]);
                mma16816(acc[2*ng+1], al, bh4[ng][2], bh4[ng][3]);
            }
        }
        __syncthreads();
    }

    const int lr0 = wm * 16 + gid;
    const int rw0 = row0 + lr0;
    const float mv0 = mask[b * 512 + (rw0 & 511)];
    const float mv1 = mask[b * 512 + ((rw0 + 8) & 511)];
    #pragma unroll
    for (int nf = 0; nf < 8; nf++) {
        const int cb = wn * 64 + nf * 8 + 2 * tig;
        const float b0v = bo[cb], b1v = bo[cb + 1];
        *(float2*)&out[(size_t)rw0 * E_ + cb] =
            make_float2((acc[nf][0] + b0v) * mv0, (acc[nf][1] + b1v) * mv0);
        *(float2*)&out[(size_t)(rw0 + 8) * E_ + cb] =
            make_float2((acc[nf][2] + b0v) * mv1, (acc[nf][3] + b1v) * mv1);
    }
}

// ---------------------------------------------------------------------------
extern "C" void kernel_launch(void* const* d_in, const int* in_sizes, int n_in,
                              void* d_out, int out_size)
{
    const float* x    = (const float*)d_in[0];
    const float* dist = (const float*)d_in[1];
    const float* mask = (const float*)d_in[2];
    const float* Wq   = (const float*)d_in[3];
    const float* bq   = (const float*)d_in[4];
    const float* Wk   = (const float*)d_in[5];
    const float* bk   = (const float*)d_in[6];
    const float* Wv   = (const float*)d_in[7];
    const float* bv   = (const float*)d_in[8];
    const float* Wo   = (const float*)d_in[9];
    const float* bo   = (const float*)d_in[10];
    float* out = (float*)d_out;

    cudaFuncSetAttribute(qkv_mma_kernel,
                         cudaFuncAttributeMaxDynamicSharedMemorySize, SMEM_QKV);
    cudaFuncSetAttribute(attn_mma_kernel,
                         cudaFuncAttributeMaxDynamicSharedMemorySize, SMEM_ATTN);
    cudaFuncSetAttribute(oproj_mma_kernel,
                         cudaFuncAttributeMaxDynamicSharedMemorySize, SMEM_OPROJ);

    wsplit_kernel<<<256, 256>>>(Wo);
    qkv_mma_kernel<<<dim3(64, 8, 3), 256, SMEM_QKV>>>(x, Wq, bq, Wk, bk, Wv, bv);
    attn_mma_kernel<<<dim3(4, 128), 256, SMEM_ATTN>>>(dist, mask);
    oproj_mma_kernel<<<128, 256, SMEM_OPROJ>>>(bo, mask, out);
}